// round 8
// baseline (speedup 1.0000x reference)
#include <cuda_runtime.h>
#include <math.h>

typedef unsigned long long u64;
#define DI __device__ __forceinline__

// ---------------- packed f32x2 helpers (FFMA2 only via PTX) ----------------
DI u64 pk2(float x, float y){ u64 r; asm("mov.b64 %0,{%1,%2};" : "=l"(r) : "f"(x), "f"(y)); return r; }
DI void upk2(u64 v, float& x, float& y){ asm("mov.b64 {%0,%1},%2;" : "=f"(x), "=f"(y) : "l"(v)); }
DI u64 ffma2(u64 a, u64 b, u64 c){ u64 d; asm("fma.rn.f32x2 %0,%1,%2,%3;" : "=l"(d) : "l"(a), "l"(b), "l"(c)); return d; }

DI float wsum(float v){
#pragma unroll
  for(int o=16;o;o>>=1) v += __shfl_xor_sync(0xffffffffu, v, o);
  return v;
}
DI float wmax(float v){
#pragma unroll
  for(int o=16;o;o>>=1) v = fmaxf(v, __shfl_xor_sync(0xffffffffu, v, o));
  return v;
}

// Shapes: B=8, H=W=128, N=16384, C=64, heads=1, hd=64, R=8, Nr=256, HID=256

// ---------------- scratch (device globals: allocation-free) ----------------
__device__ float g_h  [8*16384*64];   // LN1 output
__device__ float g_q  [8*16384*64];   // q projection (pre-scaled by 1/8)
__device__ float g_o  [8*16384*64];   // attention output
__device__ float g_xrp[8*2048*64];    // SR conv partials per ky (deterministic K-split)
__device__ float g_kT [8*64*256];     // K transposed: [b][c][m]
__device__ float g_v  [8*256*64];     // V: [b][m][c]
__device__ float g_f  [8*16384*256];  // fc1 output

// =====================================================================
// kA: LN1 + q projection (scale 1/8 folded in). 1 warp per row.
// =====================================================================
__global__ void __launch_bounds__(256) kA(const float* __restrict__ x,
    const float* __restrict__ g1, const float* __restrict__ b1,
    const float* __restrict__ qw, const float* __restrict__ qb){
  __shared__ float qws[64*64];
  __shared__ float hs[8][64];
  __shared__ float gs[64], bs[64], qbs[64];
  int t = threadIdx.x;
  for (int i=t;i<4096;i+=256) qws[i]=qw[i];
  if (t<64){ gs[t]=g1[t]; bs[t]=b1[t]; qbs[t]=qb[t]; }
  __syncthreads();
  int w=t>>5, l=t&31;
  int row = blockIdx.x*8 + w;
  const float2 xv = *(const float2*)(x + row*64 + 2*l);
  float m  = wsum(xv.x + xv.y) * (1.f/64.f);
  float s2 = wsum(xv.x*xv.x + xv.y*xv.y) * (1.f/64.f);
  float rs = rsqrtf(fmaxf(s2 - m*m, 0.f) + 1e-5f);
  float h0 = (xv.x - m)*rs*gs[2*l]   + bs[2*l];
  float h1 = (xv.y - m)*rs*gs[2*l+1] + bs[2*l+1];
  *(float2*)(g_h + row*64 + 2*l) = make_float2(h0, h1);
  hs[w][2*l] = h0; hs[w][2*l+1] = h1;
  __syncwarp();
  u64 acc = pk2(qbs[2*l], qbs[2*l+1]);
#pragma unroll 16
  for (int k=0;k<64;k++){
    float hv = hs[w][k];
    const float2 wv = *(const float2*)(qws + k*64 + 2*l);
    acc = ffma2(pk2(hv,hv), pk2(wv.x,wv.y), acc);
  }
  float o0,o1; upk2(acc,o0,o1);
  *(float2*)(g_q + row*64 + 2*l) = make_float2(o0*0.125f, o1*0.125f);
}

// =====================================================================
// kB: SR conv as GEMM M=2048,K=4096,N=64. grid(64,8): 32 rows x 64 cols,
// K split by ky into deterministic partial buffers (no atomics).
// Thread: 4 rows (g,g+8,g+16,g+24) x 2 cols (f32x2).
// =====================================================================
__global__ void __launch_bounds__(256) kB(const float* __restrict__ srw){
  __shared__ float As[32*64];
  __shared__ float Ws[64*64];
  int t = threadIdx.x;
  int m0 = blockIdx.x*32;
  int ky = blockIdx.y;
  int g = t>>5, l = t&31;
  int c2 = l*2;
  int b = m0 >> 8;   // same batch for whole block (8 blocks per 256-row batch)
  u64 acc[4] = {0,0,0,0};
  for (int kx=0; kx<8; kx++){
    for (int i2=t; i2<1024; i2+=256){
      int r = i2>>5; int ci = (i2&31)*2;
      int mm = (m0 + r) & 255;
      int oy = mm>>4, ox = mm&15;
      const float2 v = *(const float2*)(g_h + ((b*16384) + (oy*8+ky)*128 + (ox*8+kx))*64 + ci);
      *(float2*)(As + r*64 + ci) = v;
    }
    const float* wsl = srw + ((ky*8+kx)*64)*64;
    for (int i2=t; i2<2048; i2+=256)
      *(float2*)(Ws + i2*2) = *(const float2*)(wsl + i2*2);
    __syncthreads();
#pragma unroll 8
    for (int ci=0; ci<64; ci++){
      const float2 w2 = *(const float2*)(Ws + ci*64 + c2);
      u64 wp = pk2(w2.x, w2.y);
#pragma unroll
      for (int j=0;j<4;j++){
        float a = As[(g + 8*j)*64 + ci];
        acc[j] = ffma2(pk2(a,a), wp, acc[j]);
      }
    }
    __syncthreads();
  }
#pragma unroll
  for (int j=0;j<4;j++){
    float o0,o1; upk2(acc[j],o0,o1);
    *(float2*)(g_xrp + ((ky*2048) + m0 + g + 8*j)*64 + c2) = make_float2(o0,o1);
  }
}

// =====================================================================
// kC: sum conv partials + sr_b + LN(srn) + kv projection.
// Writes K transposed [b][c][m] and V [b][m][c]. 1 warp per row (2048 rows).
// =====================================================================
__global__ void __launch_bounds__(256) kC(const float* __restrict__ srb,
    const float* __restrict__ sg, const float* __restrict__ sb,
    const float* __restrict__ kvw, const float* __restrict__ kvb){
  __shared__ float kws[64*128];
  __shared__ float hs[8][64];
  int t = threadIdx.x;
  for (int i=t;i<8192;i+=256) kws[i]=kvw[i];
  __syncthreads();
  int w=t>>5, l=t&31;
  int m = blockIdx.x*8 + w;   // 0..2047
  float v0 = srb[2*l], v1 = srb[2*l+1];
#pragma unroll
  for (int p=0;p<8;p++){
    const float2 a = *(const float2*)(g_xrp + (p*2048+m)*64 + 2*l);
    v0 += a.x; v1 += a.y;
  }
  float mn = wsum(v0+v1)*(1.f/64.f);
  float s2 = wsum(v0*v0+v1*v1)*(1.f/64.f);
  float rs = rsqrtf(fmaxf(s2-mn*mn,0.f)+1e-5f);
  float h0 = (v0-mn)*rs*sg[2*l]+sb[2*l];
  float h1 = (v1-mn)*rs*sg[2*l+1]+sb[2*l+1];
  hs[w][2*l]=h0; hs[w][2*l+1]=h1;
  __syncwarp();
  u64 ak = pk2(kvb[2*l], kvb[2*l+1]);
  u64 av = pk2(kvb[64+2*l], kvb[64+2*l+1]);
#pragma unroll 8
  for (int k=0;k<64;k++){
    float hb = hs[w][k];
    u64 hp = pk2(hb,hb);
    const float2 wk = *(const float2*)(kws + k*128 + 2*l);
    const float2 wv = *(const float2*)(kws + k*128 + 64 + 2*l);
    ak = ffma2(hp, pk2(wk.x,wk.y), ak);
    av = ffma2(hp, pk2(wv.x,wv.y), av);
  }
  int b = m>>8, mm = m&255;
  float k0,k1,vv0,vv1; upk2(ak,k0,k1); upk2(av,vv0,vv1);
  g_kT[(b*64 + 2*l  )*256 + mm] = k0;
  g_kT[(b*64 + 2*l+1)*256 + mm] = k1;
  *(float2*)(g_v + m*64 + 2*l) = make_float2(vv0,vv1);
}

// =====================================================================
// kD: attention. Block = 256 thr = 8 warps, 128 queries. K^T, V, q-stage,
// p-stage in 208KB dynamic smem. Warp does 2 rounds of 8 queries.
// =====================================================================
__global__ void __launch_bounds__(256) kD(){
  extern __shared__ float sm[];
  float* Kt  = sm;                  // [64][256]
  float* Vs  = Kt + 64*256;         // [256][64]
  float* qst = Vs + 256*64;         // [8 warps][8 q][64]
  float* pst = qst + 8*8*64;        // [8 warps][8 q][256]
  int t = threadIdx.x;
  int q0 = blockIdx.x*128;
  int b  = blockIdx.x >> 7;         // 128 tiles per batch
  {
    const float4* ks = (const float4*)(g_kT + b*16384);
    const float4* vv = (const float4*)(g_v  + b*16384);
    float4* K4 = (float4*)Kt; float4* V4 = (float4*)Vs;
    for (int i=t;i<4096;i+=256){ K4[i]=ks[i]; V4[i]=vv[i]; }
  }
  __syncthreads();
  int w=t>>5, l=t&31;
  float* qw_ = qst + w*8*64;
  float* pw_ = pst + w*8*256;
  for (int rr=0; rr<2; rr++){
    int qb = q0 + w*16 + rr*8;
#pragma unroll
    for (int qi=0;qi<8;qi++)
      *(float2*)(qw_ + qi*64 + 2*l) = *(const float2*)(g_q + (qb+qi)*64 + 2*l);
    __syncwarp();
    // ---- QK: lane owns keys m = {64j+2l, 64j+2l+1}, j=0..3
    u64 s[8][4];
#pragma unroll
    for (int qi=0;qi<8;qi++){ s[qi][0]=0; s[qi][1]=0; s[qi][2]=0; s[qi][3]=0; }
    for (int c=0;c<64;c++){
      const float2* krow = (const float2*)(Kt + c*256);
      u64 kp[4];
#pragma unroll
      for (int j=0;j<4;j++){ float2 kk = krow[l + 32*j]; kp[j]=pk2(kk.x,kk.y); }
#pragma unroll
      for (int qi=0;qi<8;qi++){
        float qc = qw_[qi*64 + c];
        u64 qp = pk2(qc,qc);
#pragma unroll
        for (int j=0;j<4;j++) s[qi][j]=ffma2(qp, kp[j], s[qi][j]);
      }
    }
    // ---- softmax -> normalized p into pst
#pragma unroll
    for (int qi=0;qi<8;qi++){
      float sc[8];
#pragma unroll
      for (int j=0;j<4;j++) upk2(s[qi][j], sc[2*j], sc[2*j+1]);
      float mx = sc[0];
#pragma unroll
      for (int i=1;i<8;i++) mx = fmaxf(mx, sc[i]);
      mx = wmax(mx);
      float sum = 0.f;
#pragma unroll
      for (int i=0;i<8;i++){ sc[i]=__expf(sc[i]-mx); sum += sc[i]; }
      sum = wsum(sum);
      float inv = __frcp_rn(sum);
#pragma unroll
      for (int j=0;j<4;j++)
        *(float2*)(pw_ + qi*256 + 64*j + 2*l) = make_float2(sc[2*j]*inv, sc[2*j+1]*inv);
    }
    __syncwarp();
    // ---- AV: lane owns out cols (2l, 2l+1)
    u64 o[8];
#pragma unroll
    for (int qi=0;qi<8;qi++) o[qi]=0;
    for (int m=0;m<256;m+=2){
      float2 va = *(const float2*)(Vs + m*64 + 2*l);
      float2 vb = *(const float2*)(Vs + (m+1)*64 + 2*l);
      u64 vpa = pk2(va.x,va.y), vpb = pk2(vb.x,vb.y);
#pragma unroll
      for (int qi=0;qi<8;qi++){
        float2 pp = *(const float2*)(pw_ + qi*256 + m);
        o[qi] = ffma2(pk2(pp.x,pp.x), vpa, o[qi]);
        o[qi] = ffma2(pk2(pp.y,pp.y), vpb, o[qi]);
      }
    }
#pragma unroll
    for (int qi=0;qi<8;qi++){
      float o0,o1; upk2(o[qi],o0,o1);
      *(float2*)(g_o + (qb+qi)*64 + 2*l) = make_float2(o0,o1);
    }
    __syncwarp();
  }
}

// =====================================================================
// kE: x_new = x + o@proj_w + proj_b  (-> d_out), then LN2 + fc1 -> g_f.
// 1 warp per row; proj_w + fc1_w in dynamic smem (84KB).
// =====================================================================
__global__ void __launch_bounds__(256) kE(const float* __restrict__ x,
    const float* __restrict__ pw, const float* __restrict__ pb,
    const float* __restrict__ l2g, const float* __restrict__ l2b,
    const float* __restrict__ f1w, const float* __restrict__ f1b,
    float* __restrict__ out){
  extern __shared__ float sm[];
  float* pws  = sm;            // 4096
  float* f1ws = pws + 4096;    // 16384
  float* hs   = f1ws + 16384;  // 8*64
  int t = threadIdx.x;
  for (int i=t;i<4096;i+=256)  pws[i]=pw[i];
  for (int i=t;i<16384;i+=256) f1ws[i]=f1w[i];
  __syncthreads();
  int w=t>>5, l=t&31;
  float* hw = hs + w*64;
  int n = blockIdx.x*8 + w;
  // stage o row
  float2 o2 = *(const float2*)(g_o + n*64 + 2*l);
  hw[2*l]=o2.x; hw[2*l+1]=o2.y;
  __syncwarp();
  u64 acc = pk2(pb[2*l], pb[2*l+1]);
#pragma unroll 16
  for (int k=0;k<64;k++){
    float ob = hw[k];
    const float2 w2 = *(const float2*)(pws + k*64 + 2*l);
    acc = ffma2(pk2(ob,ob), pk2(w2.x,w2.y), acc);
  }
  float2 xv = *(const float2*)(x + n*64 + 2*l);
  float a0,a1; upk2(acc,a0,a1);
  float xn0 = xv.x + a0, xn1 = xv.y + a1;
  *(float2*)(out + n*64 + 2*l) = make_float2(xn0,xn1);
  // LN2 (register path)
  float mn = wsum(xn0+xn1)*(1.f/64.f);
  float s2 = wsum(xn0*xn0+xn1*xn1)*(1.f/64.f);
  float rs = rsqrtf(fmaxf(s2-mn*mn,0.f)+1e-5f);
  float h0 = (xn0-mn)*rs*l2g[2*l]+l2b[2*l];
  float h1 = (xn1-mn)*rs*l2g[2*l+1]+l2b[2*l+1];
  __syncwarp();                // all lanes done reading o-row
  hw[2*l]=h0; hw[2*l+1]=h1;
  __syncwarp();
  // fc1: lane owns cols 2*(32j+l), j=0..3
  u64 f[4];
#pragma unroll
  for (int j=0;j<4;j++){ int cc = 2*(32*j+l); f[j]=pk2(f1b[cc], f1b[cc+1]); }
#pragma unroll 8
  for (int k=0;k<64;k++){
    float hb = hw[k];
    u64 hp = pk2(hb,hb);
#pragma unroll
    for (int j=0;j<4;j++){
      const float2 w2 = *(const float2*)(f1ws + k*256 + 2*(32*j+l));
      f[j]=ffma2(hp, pk2(w2.x,w2.y), f[j]);
    }
  }
#pragma unroll
  for (int j=0;j<4;j++){
    float u,v; upk2(f[j],u,v);
    *(float2*)(g_f + n*256 + 2*(32*j+l)) = make_float2(u,v);
  }
}

// =====================================================================
// kG: 3x3 depthwise (SAME) + exact GELU + fc2 + residual into d_out.
// Block handles 32 pixels of one row; channels in 4 chunks of 64.
// =====================================================================
__global__ void __launch_bounds__(256) kG(const float* __restrict__ dww,
    const float* __restrict__ f2w, const float* __restrict__ f2b,
    float* __restrict__ out){
  extern __shared__ float sm[];
  float* f2ws = sm;               // 16384
  float* fs   = f2ws + 16384;     // 3*34*64 = 6528
  float* gsm  = fs + 6528;        // 32*64
  int t = threadIdx.x;
  for (int i=t;i<16384;i+=256) f2ws[i]=f2w[i];
  int w=t>>5, l=t&31;
  int bx = blockIdx.x;
  int b  = bx >> 9;               // 512 segments per batch
  int sb = bx & 511;
  int y  = sb >> 2;
  int x0 = (sb & 3)*32;
  u64 oacc[4] = {0,0,0,0};
  for (int cc=0; cc<4; cc++){
    int ch0 = cc*64;
    __syncthreads();              // covers f2ws load on iter 0; fs/gsm reuse after
    for (int i2=t; i2<3264; i2+=256){
      int c  = (i2 & 31)*2;
      int pr = i2 >> 5;           // 0..101
      int px = pr % 34;
      int ry = pr / 34;           // 0..2
      int gy = y - 1 + ry;
      int gx = x0 - 1 + px;
      float2 v = make_float2(0.f,0.f);
      if ((unsigned)gy < 128u && (unsigned)gx < 128u)
        v = *(const float2*)(g_f + ((b*16384) + gy*128 + gx)*256 + ch0 + c);
      *(float2*)(fs + (ry*34 + px)*64 + c) = v;
    }
    float2 dwr[9];
#pragma unroll
    for (int kk=0;kk<9;kk++) dwr[kk] = *(const float2*)(dww + kk*256 + ch0 + 2*l);
    __syncthreads();
#pragma unroll
    for (int p=0;p<4;p++){
      int P = w*4 + p;
      u64 ga = 0;
#pragma unroll
      for (int ky=0;ky<3;ky++)
#pragma unroll
        for (int kx=0;kx<3;kx++){
          float2 fv = *(const float2*)(fs + (ky*34 + P + kx)*64 + 2*l);
          ga = ffma2(pk2(fv.x,fv.y), pk2(dwr[ky*3+kx].x, dwr[ky*3+kx].y), ga);
        }
      float v0,v1; upk2(ga,v0,v1);
      v0 = 0.5f*v0*(1.f + erff(v0*0.70710678118f));
      v1 = 0.5f*v1*(1.f + erff(v1*0.70710678118f));
      *(float2*)(gsm + P*64 + 2*l) = make_float2(v0,v1);
    }
    __syncwarp();
#pragma unroll
    for (int p=0;p<4;p++){
      int P = w*4 + p;
#pragma unroll 8
      for (int k=0;k<64;k++){
        float gb = gsm[P*64 + k];
        const float2 w2 = *(const float2*)(f2ws + (ch0+k)*64 + 2*l);
        oacc[p] = ffma2(pk2(gb,gb), pk2(w2.x,w2.y), oacc[p]);
      }
    }
  }
  float2 bb = *(const float2*)(f2b + 2*l);
#pragma unroll
  for (int p=0;p<4;p++){
    int P = w*4 + p;
    int idx = ((b*16384) + y*128 + x0 + P)*64 + 2*l;
    float2 r = *(float2*)(out + idx);
    float a0,a1; upk2(oacc[p],a0,a1);
    *(float2*)(out + idx) = make_float2(r.x + a0 + bb.x, r.y + a1 + bb.y);
  }
}

// =====================================================================
extern "C" void kernel_launch(void* const* d_in, const int* in_sizes, int n_in,
                              void* d_out, int out_size){
  const float* x    = (const float*)d_in[0];
  // d_in[1]=H, d_in[2]=W (compile-time 128)
  const float* ln1g = (const float*)d_in[3];
  const float* ln1b = (const float*)d_in[4];
  const float* qw   = (const float*)d_in[5];
  const float* qb   = (const float*)d_in[6];
  const float* kvw  = (const float*)d_in[7];
  const float* kvb  = (const float*)d_in[8];
  const float* pw   = (const float*)d_in[9];
  const float* pb   = (const float*)d_in[10];
  const float* srw  = (const float*)d_in[11];
  const float* srb  = (const float*)d_in[12];
  const float* sng  = (const float*)d_in[13];
  const float* snb  = (const float*)d_in[14];
  const float* l2g  = (const float*)d_in[15];
  const float* l2b  = (const float*)d_in[16];
  const float* f1w  = (const float*)d_in[17];
  const float* f1b  = (const float*)d_in[18];
  const float* dww  = (const float*)d_in[19];
  const float* f2w  = (const float*)d_in[20];
  const float* f2b  = (const float*)d_in[21];
  float* out = (float*)d_out;

  size_t smD = (size_t)(64*256 + 256*64 + 8*8*64 + 8*8*256) * sizeof(float); // 208 KB
  size_t smE = (size_t)(4096 + 16384 + 8*64) * sizeof(float);                // 84 KB
  size_t smG = (size_t)(16384 + 3*34*64 + 32*64) * sizeof(float);            // ~100 KB
  cudaFuncSetAttribute(kD, cudaFuncAttributeMaxDynamicSharedMemorySize, (int)smD);
  cudaFuncSetAttribute(kE, cudaFuncAttributeMaxDynamicSharedMemorySize, (int)smE);
  cudaFuncSetAttribute(kG, cudaFuncAttributeMaxDynamicSharedMemorySize, (int)smG);

  kA<<<16384, 256>>>(x, ln1g, ln1b, qw, qb);
  kB<<<dim3(64,8), 256>>>(srw);
  kC<<<256, 256>>>(srb, sng, snb, kvw, kvb);
  kD<<<1024, 256, smD>>>();
  kE<<<16384, 256, smE>>>(x, pw, pb, l2g, l2b, f1w, f1b, out);
  kG<<<4096, 256, smG>>>(dww, f2w, f2b, out);
}

// round 10
// speedup vs baseline: 1.6361x; 1.6361x over previous
#include <cuda_runtime.h>
#include <math.h>

typedef unsigned long long u64;
#define DI __device__ __forceinline__

// ---------------- packed f32x2 helpers (FFMA2 only via PTX) ----------------
DI u64 pk2(float x, float y){ u64 r; asm("mov.b64 %0,{%1,%2};" : "=l"(r) : "f"(x), "f"(y)); return r; }
DI void upk2(u64 v, float& x, float& y){ asm("mov.b64 {%0,%1},%2;" : "=f"(x), "=f"(y) : "l"(v)); }
DI u64 ffma2(u64 a, u64 b, u64 c){ u64 d; asm("fma.rn.f32x2 %0,%1,%2,%3;" : "=l"(d) : "l"(a), "l"(b), "l"(c)); return d; }

DI float wsum(float v){
#pragma unroll
  for(int o=16;o;o>>=1) v += __shfl_xor_sync(0xffffffffu, v, o);
  return v;
}
DI float wmax(float v){
#pragma unroll
  for(int o=16;o;o>>=1) v = fmaxf(v, __shfl_xor_sync(0xffffffffu, v, o));
  return v;
}

// Shapes: B=8, H=W=128, N=16384, C=64, heads=1, hd=64, R=8, Nr=256, HID=256

// ---------------- scratch (device globals: allocation-free) ----------------
__device__ float g_h  [8*16384*64];   // LN1 output
__device__ float g_q  [8*16384*64];   // q projection (pre-scaled by 1/8)
__device__ float g_o  [8*16384*64];   // attention output
__device__ float g_xrp[8*2048*64];    // SR conv partials per ky
__device__ float g_kT [8*64*256];     // K transposed: [b][c][m]
__device__ float g_v  [8*256*64];     // V: [b][m][c]
__device__ float g_f  [8*16384*256];  // fc1 output

// =====================================================================
// kA: LN1 + q projection. Warp handles 8 rows; block = 64 rows/iter.
// grid 1024, 2 iterations -> weights staged once per block.
// =====================================================================
__global__ void __launch_bounds__(256) kA(const float* __restrict__ x,
    const float* __restrict__ g1, const float* __restrict__ b1,
    const float* __restrict__ qw, const float* __restrict__ qb){
  __shared__ float qws[64*64];
  __shared__ float hs[8][8*64];
  __shared__ float gs[64], bs[64], qbs[64];
  int t = threadIdx.x;
  for (int i=t;i<4096;i+=256) qws[i]=qw[i];
  if (t<64){ gs[t]=g1[t]; bs[t]=b1[t]; qbs[t]=qb[t]; }
  __syncthreads();
  int w=t>>5, l=t&31;
  float* hw = hs[w];
  float g0=gs[2*l], g1v=gs[2*l+1], b0=bs[2*l], b1v=bs[2*l+1];
  u64 qbp = pk2(qbs[2*l], qbs[2*l+1]);
  for (int task=blockIdx.x; task<2048; task+=1024){
    int base = task*64 + w*8;
#pragma unroll
    for (int i=0;i<8;i++){
      const float2 xv = *(const float2*)(x + (base+i)*64 + 2*l);
      float m  = wsum(xv.x + xv.y) * (1.f/64.f);
      float s2 = wsum(xv.x*xv.x + xv.y*xv.y) * (1.f/64.f);
      float rs = rsqrtf(fmaxf(s2 - m*m, 0.f) + 1e-5f);
      float h0 = (xv.x - m)*rs*g0 + b0;
      float h1 = (xv.y - m)*rs*g1v + b1v;
      *(float2*)(g_h + (base+i)*64 + 2*l) = make_float2(h0, h1);
      hw[i*64 + 2*l] = h0; hw[i*64 + 2*l+1] = h1;
    }
    __syncwarp();
    u64 acc[8];
#pragma unroll
    for (int i=0;i<8;i++) acc[i]=qbp;
#pragma unroll 8
    for (int k=0;k<64;k++){
      const float2 wv = *(const float2*)(qws + k*64 + 2*l);
      u64 wp = pk2(wv.x, wv.y);
#pragma unroll
      for (int i=0;i<8;i++){
        float hv = hw[i*64 + k];
        acc[i] = ffma2(pk2(hv,hv), wp, acc[i]);
      }
    }
#pragma unroll
    for (int i=0;i<8;i++){
      float o0,o1; upk2(acc[i],o0,o1);
      *(float2*)(g_q + (base+i)*64 + 2*l) = make_float2(o0*0.125f, o1*0.125f);
    }
    __syncwarp();
  }
}

// =====================================================================
// kB: SR conv as GEMM M=2048,K=4096,N=64. grid(64,8), K split by ky.
// =====================================================================
__global__ void __launch_bounds__(256) kB(const float* __restrict__ srw){
  __shared__ float As[32*64];
  __shared__ float Ws[64*64];
  int t = threadIdx.x;
  int m0 = blockIdx.x*32;
  int ky = blockIdx.y;
  int g = t>>5, l = t&31;
  int c2 = l*2;
  int b = m0 >> 8;
  u64 acc[4] = {0,0,0,0};
  for (int kx=0; kx<8; kx++){
    for (int i2=t; i2<1024; i2+=256){
      int r = i2>>5; int ci = (i2&31)*2;
      int mm = (m0 + r) & 255;
      int oy = mm>>4, ox = mm&15;
      const float2 v = *(const float2*)(g_h + ((b*16384) + (oy*8+ky)*128 + (ox*8+kx))*64 + ci);
      *(float2*)(As + r*64 + ci) = v;
    }
    const float* wsl = srw + ((ky*8+kx)*64)*64;
    for (int i2=t; i2<2048; i2+=256)
      *(float2*)(Ws + i2*2) = *(const float2*)(wsl + i2*2);
    __syncthreads();
#pragma unroll 8
    for (int ci=0; ci<64; ci++){
      const float2 w2 = *(const float2*)(Ws + ci*64 + c2);
      u64 wp = pk2(w2.x, w2.y);
#pragma unroll
      for (int j=0;j<4;j++){
        float a = As[(g + 8*j)*64 + ci];
        acc[j] = ffma2(pk2(a,a), wp, acc[j]);
      }
    }
    __syncthreads();
  }
#pragma unroll
  for (int j=0;j<4;j++){
    float o0,o1; upk2(acc[j],o0,o1);
    *(float2*)(g_xrp + ((ky*2048) + m0 + g + 8*j)*64 + c2) = make_float2(o0,o1);
  }
}

// =====================================================================
// kC: sum conv partials + sr_b + LN + kv projection. K transposed out.
// =====================================================================
__global__ void __launch_bounds__(256) kC(const float* __restrict__ srb,
    const float* __restrict__ sg, const float* __restrict__ sb,
    const float* __restrict__ kvw, const float* __restrict__ kvb){
  __shared__ float kws[64*128];
  __shared__ float hs[8][64];
  int t = threadIdx.x;
  for (int i=t;i<8192;i+=256) kws[i]=kvw[i];
  __syncthreads();
  int w=t>>5, l=t&31;
  int m = blockIdx.x*8 + w;
  float v0 = srb[2*l], v1 = srb[2*l+1];
#pragma unroll
  for (int p=0;p<8;p++){
    const float2 a = *(const float2*)(g_xrp + (p*2048+m)*64 + 2*l);
    v0 += a.x; v1 += a.y;
  }
  float mn = wsum(v0+v1)*(1.f/64.f);
  float s2 = wsum(v0*v0+v1*v1)*(1.f/64.f);
  float rs = rsqrtf(fmaxf(s2-mn*mn,0.f)+1e-5f);
  float h0 = (v0-mn)*rs*sg[2*l]+sb[2*l];
  float h1 = (v1-mn)*rs*sg[2*l+1]+sb[2*l+1];
  hs[w][2*l]=h0; hs[w][2*l+1]=h1;
  __syncwarp();
  u64 ak = pk2(kvb[2*l], kvb[2*l+1]);
  u64 av = pk2(kvb[64+2*l], kvb[64+2*l+1]);
#pragma unroll 8
  for (int k=0;k<64;k++){
    float hb = hs[w][k];
    u64 hp = pk2(hb,hb);
    const float2 wk = *(const float2*)(kws + k*128 + 2*l);
    const float2 wv = *(const float2*)(kws + k*128 + 64 + 2*l);
    ak = ffma2(hp, pk2(wk.x,wk.y), ak);
    av = ffma2(hp, pk2(wv.x,wv.y), av);
  }
  int b = m>>8, mm = m&255;
  float k0,k1,vv0,vv1; upk2(ak,k0,k1); upk2(av,vv0,vv1);
  g_kT[(b*64 + 2*l  )*256 + mm] = k0;
  g_kT[(b*64 + 2*l+1)*256 + mm] = k1;
  *(float2*)(g_v + m*64 + 2*l) = make_float2(vv0,vv1);
}

// =====================================================================
// kD: attention. 512 thr = 16 warps x 8 queries = 128 q/block.
// Phase-split smem: one 64KB buffer holds K^T during QK, V during AV.
// smem = 64 + 32 + 128 = 224KB.
// =====================================================================
__global__ void __launch_bounds__(512) kD(){
  extern __shared__ float sm[];
  float* KV  = sm;                  // [64][256] as K^T, then [256][64] as V
  float* qst = KV + 16384;          // [16 warps][8 q][64]
  float* pst = qst + 16*8*64;       // [16 warps][8 q][256]
  int t = threadIdx.x;
  int b  = blockIdx.x >> 7;
  int q0 = blockIdx.x*128;
  int w=t>>5, l=t&31;
  float* qw_ = qst + w*512;
  float* pw_ = pst + w*2048;
  int qb = q0 + w*8;
  // load K^T + stage q
  {
    const float4* ks = (const float4*)(g_kT + b*16384);
    float4* K4 = (float4*)KV;
    for (int i=t;i<4096;i+=512) K4[i]=ks[i];
  }
#pragma unroll
  for (int qi=0;qi<8;qi++)
    *(float2*)(qw_ + qi*64 + 2*l) = *(const float2*)(g_q + (qb+qi)*64 + 2*l);
  __syncthreads();
  // ---- QK: lane owns keys m = {64j+2l, 64j+2l+1}
  u64 s[8][4];
#pragma unroll
  for (int qi=0;qi<8;qi++){ s[qi][0]=0; s[qi][1]=0; s[qi][2]=0; s[qi][3]=0; }
  for (int c=0;c<64;c++){
    const float2* krow = (const float2*)(KV + c*256);
    u64 kp[4];
#pragma unroll
    for (int j=0;j<4;j++){ float2 kk = krow[l + 32*j]; kp[j]=pk2(kk.x,kk.y); }
#pragma unroll
    for (int qi=0;qi<8;qi++){
      float qc = qw_[qi*64 + c];
      u64 qp = pk2(qc,qc);
#pragma unroll
      for (int j=0;j<4;j++) s[qi][j]=ffma2(qp, kp[j], s[qi][j]);
    }
  }
  // ---- softmax -> normalized p into pst
#pragma unroll
  for (int qi=0;qi<8;qi++){
    float sc[8];
#pragma unroll
    for (int j=0;j<4;j++) upk2(s[qi][j], sc[2*j], sc[2*j+1]);
    float mx = sc[0];
#pragma unroll
    for (int i=1;i<8;i++) mx = fmaxf(mx, sc[i]);
    mx = wmax(mx);
    float sum = 0.f;
#pragma unroll
    for (int i=0;i<8;i++){ sc[i]=__expf(sc[i]-mx); sum += sc[i]; }
    sum = wsum(sum);
    float inv = __frcp_rn(sum);
#pragma unroll
    for (int j=0;j<4;j++)
      *(float2*)(pw_ + qi*256 + 64*j + 2*l) = make_float2(sc[2*j]*inv, sc[2*j+1]*inv);
  }
  __syncthreads();               // everyone done reading K^T
  // ---- reload buffer with V
  {
    const float4* vv = (const float4*)(g_v + b*16384);
    float4* V4 = (float4*)KV;
    for (int i=t;i<4096;i+=512) V4[i]=vv[i];
  }
  __syncthreads();
  // ---- AV: lane owns out cols (2l, 2l+1)
  u64 o[8];
#pragma unroll
  for (int qi=0;qi<8;qi++) o[qi]=0;
  for (int m=0;m<256;m+=2){
    float2 va = *(const float2*)(KV + m*64 + 2*l);
    float2 vb = *(const float2*)(KV + (m+1)*64 + 2*l);
    u64 vpa = pk2(va.x,va.y), vpb = pk2(vb.x,vb.y);
#pragma unroll
    for (int qi=0;qi<8;qi++){
      float2 pp = *(const float2*)(pw_ + qi*256 + m);
      o[qi] = ffma2(pk2(pp.x,pp.x), vpa, o[qi]);
      o[qi] = ffma2(pk2(pp.y,pp.y), vpb, o[qi]);
    }
  }
#pragma unroll
  for (int qi=0;qi<8;qi++){
    float o0,o1; upk2(o[qi],o0,o1);
    *(float2*)(g_o + (qb+qi)*64 + 2*l) = make_float2(o0,o1);
  }
}

// =====================================================================
// kE: x_new = x + o@proj_w + proj_b (-> d_out), LN2, fc1 -> g_f.
// Warp handles 8 rows; grid 1024, 2 iterations.
// =====================================================================
__global__ void __launch_bounds__(256) kE(const float* __restrict__ x,
    const float* __restrict__ pw, const float* __restrict__ pb,
    const float* __restrict__ l2g, const float* __restrict__ l2b,
    const float* __restrict__ f1w, const float* __restrict__ f1b,
    float* __restrict__ out){
  extern __shared__ float sm[];
  float* pws  = sm;            // 4096
  float* f1ws = pws + 4096;    // 16384
  float* hs   = f1ws + 16384;  // 8*8*64 = 4096
  int t = threadIdx.x;
  for (int i=t;i<4096;i+=256)  pws[i]=pw[i];
  for (int i=t;i<16384;i+=256) f1ws[i]=f1w[i];
  __syncthreads();
  int w=t>>5, l=t&31;
  float* hw = hs + w*512;
  const float2 pbv = *(const float2*)(pb + 2*l);
  const u64 pbp = pk2(pbv.x, pbv.y);
  const float lg0=l2g[2*l], lg1=l2g[2*l+1], lb0=l2b[2*l], lb1=l2b[2*l+1];
  u64 fbp[4];
#pragma unroll
  for (int j=0;j<4;j++){ int cc=2*(32*j+l); fbp[j]=pk2(f1b[cc], f1b[cc+1]); }
  for (int task=blockIdx.x; task<2048; task+=1024){
    int base = task*64 + w*8;
#pragma unroll
    for (int i=0;i<8;i++){
      float2 o2 = *(const float2*)(g_o + (base+i)*64 + 2*l);
      hw[i*64+2*l]=o2.x; hw[i*64+2*l+1]=o2.y;
    }
    __syncwarp();
    u64 acc[8];
#pragma unroll
    for (int i=0;i<8;i++) acc[i]=pbp;
#pragma unroll 8
    for (int k=0;k<64;k++){
      const float2 w2 = *(const float2*)(pws + k*64 + 2*l);
      u64 wp = pk2(w2.x,w2.y);
#pragma unroll
      for (int i=0;i<8;i++){
        float ob = hw[i*64+k];
        acc[i] = ffma2(pk2(ob,ob), wp, acc[i]);
      }
    }
    float h0v[8], h1v[8];
#pragma unroll
    for (int i=0;i<8;i++){
      float2 xv = *(const float2*)(x + (base+i)*64 + 2*l);
      float a0,a1; upk2(acc[i],a0,a1);
      float xn0 = xv.x + a0, xn1 = xv.y + a1;
      *(float2*)(out + (base+i)*64 + 2*l) = make_float2(xn0,xn1);
      float mn = wsum(xn0+xn1)*(1.f/64.f);
      float s2 = wsum(xn0*xn0+xn1*xn1)*(1.f/64.f);
      float rs = rsqrtf(fmaxf(s2-mn*mn,0.f)+1e-5f);
      h0v[i] = (xn0-mn)*rs*lg0+lb0;
      h1v[i] = (xn1-mn)*rs*lg1+lb1;
    }
    __syncwarp();
#pragma unroll
    for (int i=0;i<8;i++){ hw[i*64+2*l]=h0v[i]; hw[i*64+2*l+1]=h1v[i]; }
    __syncwarp();
    // fc1: rows i x col-groups j (cols 2*(32j+l))
    u64 f[8][4];
#pragma unroll
    for (int i=0;i<8;i++)
#pragma unroll
      for (int j=0;j<4;j++) f[i][j]=fbp[j];
#pragma unroll 4
    for (int k=0;k<64;k++){
      u64 wp[4];
#pragma unroll
      for (int j=0;j<4;j++){
        const float2 w2 = *(const float2*)(f1ws + k*256 + 2*(32*j+l));
        wp[j]=pk2(w2.x,w2.y);
      }
#pragma unroll
      for (int i=0;i<8;i++){
        float hb = hw[i*64+k];
        u64 hp = pk2(hb,hb);
#pragma unroll
        for (int j=0;j<4;j++) f[i][j]=ffma2(hp, wp[j], f[i][j]);
      }
    }
#pragma unroll
    for (int i=0;i<8;i++)
#pragma unroll
      for (int j=0;j<4;j++){
        float u,v; upk2(f[i][j],u,v);
        *(float2*)(g_f + (base+i)*256 + 2*(32*j+l)) = make_float2(u,v);
      }
    __syncwarp();
  }
}

// =====================================================================
// kG: 3x3 depthwise (SAME) + exact GELU + fc2 + residual into d_out.
// grid 1024, loops over 4096 segments; f2w staged once per block.
// =====================================================================
__global__ void __launch_bounds__(256) kG(const float* __restrict__ dww,
    const float* __restrict__ f2w, const float* __restrict__ f2b,
    float* __restrict__ out){
  extern __shared__ float sm[];
  float* f2ws = sm;               // 16384
  float* fs   = f2ws + 16384;     // 3*34*64 = 6528
  float* gsm  = fs + 6528;        // 32*64
  int t = threadIdx.x;
  for (int i=t;i<16384;i+=256) f2ws[i]=f2w[i];
  __syncthreads();
  int w=t>>5, l=t&31;
  const float2 bb = *(const float2*)(f2b + 2*l);
  for (int seg=blockIdx.x; seg<4096; seg+=1024){
    int b  = seg >> 9;
    int sb = seg & 511;
    int y  = sb >> 2;
    int x0 = (sb & 3)*32;
    u64 oacc[4] = {0,0,0,0};
    for (int cc=0; cc<4; cc++){
      int ch0 = cc*64;
      __syncthreads();            // previous dw-stage reads of fs complete
      for (int i2=t; i2<3264; i2+=256){
        int c  = (i2 & 31)*2;
        int pr = i2 >> 5;
        int px = pr % 34;
        int ry = pr / 34;
        int gy = y - 1 + ry;
        int gx = x0 - 1 + px;
        float2 v = make_float2(0.f,0.f);
        if ((unsigned)gy < 128u && (unsigned)gx < 128u)
          v = *(const float2*)(g_f + ((b*16384) + gy*128 + gx)*256 + ch0 + c);
        *(float2*)(fs + (ry*34 + px)*64 + c) = v;
      }
      float2 dwr[9];
#pragma unroll
      for (int kk=0;kk<9;kk++) dwr[kk] = *(const float2*)(dww + kk*256 + ch0 + 2*l);
      __syncthreads();
#pragma unroll
      for (int p=0;p<4;p++){
        int P = w*4 + p;
        u64 ga = 0;
#pragma unroll
        for (int ky=0;ky<3;ky++)
#pragma unroll
          for (int kx=0;kx<3;kx++){
            float2 fv = *(const float2*)(fs + (ky*34 + P + kx)*64 + 2*l);
            ga = ffma2(pk2(fv.x,fv.y), pk2(dwr[ky*3+kx].x, dwr[ky*3+kx].y), ga);
          }
        float v0,v1; upk2(ga,v0,v1);
        v0 = 0.5f*v0*(1.f + erff(v0*0.70710678118f));
        v1 = 0.5f*v1*(1.f + erff(v1*0.70710678118f));
        *(float2*)(gsm + P*64 + 2*l) = make_float2(v0,v1);
      }
      __syncwarp();
#pragma unroll
      for (int p=0;p<4;p++){
        int P = w*4 + p;
#pragma unroll 8
        for (int k=0;k<64;k++){
          float gb = gsm[P*64 + k];
          const float2 w2 = *(const float2*)(f2ws + (ch0+k)*64 + 2*l);
          oacc[p] = ffma2(pk2(gb,gb), pk2(w2.x,w2.y), oacc[p]);
        }
      }
      __syncwarp();
    }
#pragma unroll
    for (int p=0;p<4;p++){
      int P = w*4 + p;
      int idx = ((b*16384) + y*128 + x0 + P)*64 + 2*l;
      float2 r = *(float2*)(out + idx);
      float a0,a1; upk2(oacc[p],a0,a1);
      *(float2*)(out + idx) = make_float2(r.x + a0 + bb.x, r.y + a1 + bb.y);
    }
  }
}

// =====================================================================
extern "C" void kernel_launch(void* const* d_in, const int* in_sizes, int n_in,
                              void* d_out, int out_size){
  const float* x    = (const float*)d_in[0];
  const float* ln1g = (const float*)d_in[3];
  const float* ln1b = (const float*)d_in[4];
  const float* qw   = (const float*)d_in[5];
  const float* qb   = (const float*)d_in[6];
  const float* kvw  = (const float*)d_in[7];
  const float* kvb  = (const float*)d_in[8];
  const float* pw   = (const float*)d_in[9];
  const float* pb   = (const float*)d_in[10];
  const float* srw  = (const float*)d_in[11];
  const float* srb  = (const float*)d_in[12];
  const float* sng  = (const float*)d_in[13];
  const float* snb  = (const float*)d_in[14];
  const float* l2g  = (const float*)d_in[15];
  const float* l2b  = (const float*)d_in[16];
  const float* f1w  = (const float*)d_in[17];
  const float* f1b  = (const float*)d_in[18];
  const float* dww  = (const float*)d_in[19];
  const float* f2w  = (const float*)d_in[20];
  const float* f2b  = (const float*)d_in[21];
  float* out = (float*)d_out;

  size_t smD = (size_t)(16384 + 16*8*64 + 16*8*256) * sizeof(float); // 224 KB
  size_t smE = (size_t)(4096 + 16384 + 4096) * sizeof(float);        // 96 KB
  size_t smG = (size_t)(16384 + 3*34*64 + 32*64) * sizeof(float);    // ~98 KB
  cudaFuncSetAttribute(kD, cudaFuncAttributeMaxDynamicSharedMemorySize, (int)smD);
  cudaFuncSetAttribute(kE, cudaFuncAttributeMaxDynamicSharedMemorySize, (int)smE);
  cudaFuncSetAttribute(kG, cudaFuncAttributeMaxDynamicSharedMemorySize, (int)smG);

  kA<<<1024, 256>>>(x, ln1g, ln1b, qw, qb);
  kB<<<dim3(64,8), 256>>>(srw);
  kC<<<256, 256>>>(srb, sng, snb, kvw, kvb);
  kD<<<1024, 512, smD>>>();
  kE<<<1024, 256, smE>>>(x, pw, pb, l2g, l2b, f1w, f1b, out);
  kG<<<1024, 256, smG>>>(dww, f2w, f2b, out);
}